// round 6
// baseline (speedup 1.0000x reference)
#include <cuda_runtime.h>
#include <cuda_bf16.h>
#include <math.h>
#include <stdint.h>

#define BATCH  64
#define HD     128
#define OUTC   10

#define PITCHV 136      // V row pitch, bf16 elems
#define V_OFF  0
#define XS_OFF (16 * PITCHV * 2)            // 4352
#define LG_OFF (XS_OFF + 16 * 256 * 4)      // 20736
#define RI_OFF (LG_OFF + 64)
#define LT_OFF (RI_OFF + 64)
#define SMEM_MAIN (LT_OFF + 64)             // ~20.9 KB (static)

// chainT[m][n][k] = cores[m][k][d][h], n = 2h+d   (k-contiguous, bf16, 16.7 MB)
__device__ __nv_bfloat16 g_chainT[(size_t)255 * 256 * 128];

// ---------------- helpers ----------------
__device__ __forceinline__ uint32_t smem_u32(const void* p) {
    uint32_t a;
    asm("{ .reg .u64 t; cvta.to.shared.u64 t, %1; cvt.u32.u64 %0, t; }" : "=r"(a) : "l"(p));
    return a;
}
__device__ __forceinline__ void ldm_x4(uint32_t* r, uint32_t addr) {
    asm volatile("ldmatrix.sync.aligned.m8n8.x4.shared.b16 {%0,%1,%2,%3}, [%4];"
                 : "=r"(r[0]), "=r"(r[1]), "=r"(r[2]), "=r"(r[3]) : "r"(addr));
}
__device__ __forceinline__ void mma16816(float* c, const uint32_t* a,
                                         uint32_t b0, uint32_t b1) {
    asm volatile(
        "mma.sync.aligned.m16n8k16.row.col.f32.bf16.bf16.f32 "
        "{%0,%1,%2,%3}, {%4,%5,%6,%7}, {%8,%9}, {%0,%1,%2,%3};"
        : "+f"(c[0]), "+f"(c[1]), "+f"(c[2]), "+f"(c[3])
        : "r"(a[0]), "r"(a[1]), "r"(a[2]), "r"(a[3]), "r"(b0), "r"(b1));
}

// ---------------- pre-pass: cores (m,k,d,h) fp32 -> chainT (m, 2h+d, k) bf16 ----
__global__ void __launch_bounds__(256) conv_chainT(const float* __restrict__ cores)
{
    __shared__ __nv_bfloat16 t[128][136];   // 34.8 KB
    const int m = blockIdx.x, tid = threadIdx.x;
    const float* src = cores + (size_t)m * 32768;
    __nv_bfloat16* dst = g_chainT + (size_t)m * 32768;

    #pragma unroll
    for (int p = 0; p < 2; ++p) {           // h-halves: n rows [p*128, p*128+128)
        #pragma unroll
        for (int it = 0; it < 64; ++it) {
            int idx = it * 256 + tid;       // k*128 + d*64 + hl   (16384 elems)
            int k = idx >> 7, d = (idx >> 6) & 1, hl = idx & 63;
            t[(hl << 1) | d][k] = __float2bfloat16(src[((size_t)k * 2 + d) * 128 + p * 64 + hl]);
        }
        __syncthreads();
        #pragma unroll
        for (int it = 0; it < 8; ++it) {
            int idx = it * 256 + tid;       // nl*16 + kchunk (2048 uint4)
            int nl = idx >> 4, kb = (idx & 15) * 8;
            *(uint4*)(dst + ((size_t)(p * 128 + nl)) * 128 + kb) = *(uint4*)(&t[nl][kb]);
        }
        __syncthreads();
    }
}

// ---------------- main: batched vector chain, B via LDG from L2 ----------------
__global__ void __launch_bounds__(256) mps_chain(
    const float* __restrict__ x, const float* __restrict__ core0,
    const float* __restrict__ classifier, float* __restrict__ out)
{
    __shared__ char sm[SMEM_MAIN];
    uint32_t smb = smem_u32(sm);
    const int tid = threadIdx.x, lane = tid & 31, wc = tid >> 5;  // warp = 32-col slice
    const int b0 = blockIdx.x * 16;

    float* XS   = (float*)(sm + XS_OFF);    // [16][256]
    float* LOGS = (float*)(sm + LG_OFF);
    float* RINV = (float*)(sm + RI_OFF);
    float* LTOT = (float*)(sm + LT_OFF);

    #pragma unroll
    for (int it = 0; it < 16; ++it) {
        int idx = it * 256 + tid;
        XS[idx] = x[(size_t)(b0 + (idx >> 8)) * 256 + (idx & 255)];
    }
    if (tid < 16) LOGS[tid] = 0.f;
    __syncthreads();

    // init V[bb][h]
    #pragma unroll
    for (int it = 0; it < 8; ++it) {
        int idx = it * 256 + tid;
        int bb = idx >> 7, h = idx & 127;
        float xv = XS[bb * 256];
        float v = (1.f - xv) * core0[h] + xv * core0[HD + h];
        *(__nv_bfloat16*)(sm + V_OFF + bb * (PITCHV * 2) + h * 2) = __float2bfloat16(v);
    }
    // first barrier in the loop makes these visible

    const int l15 = lane & 15, lhi = (lane >> 4) << 3;
    const int r = lane >> 2, q = lane & 3;
    // B-fragment addressing: n = wc*32 + nt*8 + (lane>>2); k = kc*16 + 2*(lane&3) (+8)
    const uint32_t koff = (uint32_t)(lane & 3) * 4;                  // bytes
    const uint32_t nrow0 = (uint32_t)(wc * 32 + (lane >> 2)) << 8;   // n*256 bytes

    for (int m = 0; m < 255; ++m) {
        // ---- B fragments straight from global (L2-resident), no V dependency ----
        const char* bp = (const char*)(g_chainT + (size_t)m * 32768);
        uint32_t B0[4][8], B1[4][8];
        #pragma unroll
        for (int nt = 0; nt < 4; ++nt) {
            const char* bn = bp + nrow0 + ((uint32_t)nt << 11) + koff;  // nt*8 cols * 256B
            #pragma unroll
            for (int kc = 0; kc < 8; ++kc) {
                B0[nt][kc] = *(const uint32_t*)(bn + kc * 32);
                B1[nt][kc] = *(const uint32_t*)(bn + kc * 32 + 16);
            }
        }

        __syncthreads();   // V(m) writes visible

        uint32_t A[8][4];
        #pragma unroll
        for (int kc = 0; kc < 8; ++kc)
            ldm_x4(A[kc], smb + V_OFF + (uint32_t)(l15 * PITCHV + kc * 16 + lhi) * 2);

        float acc[4][4];
        #pragma unroll
        for (int i = 0; i < 4; ++i)
            #pragma unroll
            for (int j = 0; j < 4; ++j) acc[i][j] = 0.f;

        #pragma unroll
        for (int kc = 0; kc < 8; ++kc)
            #pragma unroll
            for (int nt = 0; nt < 4; ++nt)
                mma16816(acc[nt], A[kc], B0[nt][kc], B1[nt][kc]);

        __syncthreads();   // all V reads done -> safe to overwrite

        const float xa = XS[r * 256 + m + 1];
        const float xb = XS[(r + 8) * 256 + m + 1];
        #pragma unroll
        for (int nt = 0; nt < 4; ++nt) {
            int h = wc * 16 + nt * 4 + q;
            float v0 = fmaf(xa, acc[nt][1], (1.f - xa) * acc[nt][0]);
            float v1 = fmaf(xb, acc[nt][3], (1.f - xb) * acc[nt][2]);
            *(__nv_bfloat16*)(sm + V_OFF + r * (PITCHV * 2) + h * 2) = __float2bfloat16(v0);
            *(__nv_bfloat16*)(sm + V_OFF + (r + 8) * (PITCHV * 2) + h * 2) = __float2bfloat16(v1);
        }

        if (((m + 1) & 15) == 0 && m < 254) {
            __syncthreads();
            int bb = tid >> 4, seg = tid & 15;
            __nv_bfloat16* vr = (__nv_bfloat16*)(sm + V_OFF + bb * (PITCHV * 2));
            float s = 0.f;
            #pragma unroll
            for (int j = 0; j < 8; ++j) {
                float f = __bfloat162float(vr[seg * 8 + j]);
                s = fmaf(f, f, s);
            }
            #pragma unroll
            for (int o = 8; o > 0; o >>= 1) s += __shfl_xor_sync(0xffffffffu, s, o);
            if (seg == 0) {
                float nrm = fmaxf(sqrtf(s), 1e-30f);
                LOGS[bb] += logf(nrm);
                RINV[bb] = 1.f / nrm;
            }
            __syncthreads();
            float ri = RINV[bb];
            #pragma unroll
            for (int j = 0; j < 8; ++j)
                vr[seg * 8 + j] = __float2bfloat16(__bfloat162float(vr[seg * 8 + j]) * ri);
        }
    }
    __syncthreads();

    // final norm + total log
    {
        int bb = tid >> 4, seg = tid & 15;
        const __nv_bfloat16* vr = (const __nv_bfloat16*)(sm + V_OFF + bb * (PITCHV * 2));
        float s = 0.f;
        #pragma unroll
        for (int j = 0; j < 8; ++j) {
            float f = __bfloat162float(vr[seg * 8 + j]);
            s = fmaf(f, f, s);
        }
        #pragma unroll
        for (int o = 8; o > 0; o >>= 1) s += __shfl_xor_sync(0xffffffffu, s, o);
        if (seg == 0) {
            float nrm = fmaxf(sqrtf(s), 1e-30f);
            RINV[bb] = 1.f / nrm;
            LTOT[bb] = LOGS[bb] + logf(nrm);
        }
    }
    __syncthreads();

    if (tid < 16 * OUTC) {
        int bb = tid / OUTC, o = tid % OUTC;
        const __nv_bfloat16* vr = (const __nv_bfloat16*)(sm + V_OFF + bb * (PITCHV * 2));
        float s = 0.f;
        #pragma unroll
        for (int h = 0; h < HD; ++h)
            s = fmaf(__bfloat162float(vr[h]), classifier[o * HD + h], s);
        out[(size_t)(b0 + bb) * OUTC + o] = s * RINV[bb] + LTOT[bb];
    }
}

extern "C" void kernel_launch(void* const* d_in, const int* in_sizes, int n_in,
                              void* d_out, int out_size)
{
    (void)in_sizes; (void)n_in; (void)out_size;
    const float* x          = (const float*)d_in[0];
    const float* core0      = (const float*)d_in[1];
    const float* cores      = (const float*)d_in[2];
    const float* classifier = (const float*)d_in[3];
    float*       out        = (float*)d_out;

    conv_chainT<<<255, 256>>>(cores);
    mps_chain<<<4, 256>>>(x, core0, classifier, out);
}

// round 8
// speedup vs baseline: 2.5080x; 2.5080x over previous
#include <cuda_runtime.h>
#include <cuda_bf16.h>
#include <math.h>
#include <stdint.h>

#define BATCH  64
#define HD     128
#define OUTC   10

#define PITCHV 136      // V row pitch, bf16 elems
#define V_OFF  0
#define XS_OFF (16 * PITCHV * 2)            // 4352
#define LG_OFF (XS_OFF + 16 * 256 * 4)      // 20736
#define RI_OFF (LG_OFF + 64)
#define LT_OFF (RI_OFF + 64)
#define SMEM_MAIN (LT_OFF + 64)             // ~20.9 KB (static)

// Chain matrices permuted into mma.m16n8k16 B-fragment order (bf16, 16.7 MB):
// uint32 index: (((m*8 + wc)*4 + nt)*4 + kp)*128 + lane*4 + j      [16384 u32 per m]
//   kc = 2*kp + (j>>1); reg = j&1
//   packed pair = M[k0][n], M[k0+1][n]; k0 = kc*16 + 2*(lane&3) + reg*8
//   n = wc*32 + nt*8 + (lane>>2);  M[k][2h+d] = cores[m][k][d][h]
__device__ uint32_t g_perm[(size_t)255 * 16384];

// ---------------- helpers ----------------
__device__ __forceinline__ uint32_t smem_u32(const void* p) {
    uint32_t a;
    asm("{ .reg .u64 t; cvta.to.shared.u64 t, %1; cvt.u32.u64 %0, t; }" : "=r"(a) : "l"(p));
    return a;
}
__device__ __forceinline__ void ldm_x4(uint32_t* r, uint32_t addr) {
    asm volatile("ldmatrix.sync.aligned.m8n8.x4.shared.b16 {%0,%1,%2,%3}, [%4];"
                 : "=r"(r[0]), "=r"(r[1]), "=r"(r[2]), "=r"(r[3]) : "r"(addr));
}
__device__ __forceinline__ void mma16816(float* c, const uint32_t* a,
                                         uint32_t b0, uint32_t b1) {
    asm volatile(
        "mma.sync.aligned.m16n8k16.row.col.f32.bf16.bf16.f32 "
        "{%0,%1,%2,%3}, {%4,%5,%6,%7}, {%8,%9}, {%0,%1,%2,%3};"
        : "+f"(c[0]), "+f"(c[1]), "+f"(c[2]), "+f"(c[3])
        : "r"(a[0]), "r"(a[1]), "r"(a[2]), "r"(a[3]), "r"(b0), "r"(b1));
}
__device__ __forceinline__ uint32_t packbf2(float a, float b) {
    __nv_bfloat162 t = __floats2bfloat162_rn(a, b);
    return *reinterpret_cast<uint32_t*>(&t);
}

// ---------------- pre-pass: cores fp32 -> fragment-permuted bf16 ----------------
__global__ void __launch_bounds__(256) conv_perm(const float* __restrict__ cores)
{
    size_t gid = (size_t)blockIdx.x * 256 + threadIdx.x;   // 255*16384 total
    int u = (int)(gid & 16383);
    int m = (int)(gid >> 14);
    int j    = u & 3;
    int lane = (u >> 2) & 31;
    int kp   = (u >> 7) & 3;
    int nt   = (u >> 9) & 3;
    int wc   = (u >> 11) & 7;
    int kc = 2 * kp + (j >> 1);
    int k0 = kc * 16 + 2 * (lane & 3) + ((j & 1) << 3);
    int n  = wc * 32 + nt * 8 + (lane >> 2);
    int h = n >> 1, d = n & 1;
    const float* base = cores + (size_t)m * 32768;
    float lo = base[((size_t)k0 * 2 + d) * 128 + h];
    float hi = base[((size_t)(k0 + 1) * 2 + d) * 128 + h];
    g_perm[gid] = packbf2(lo, hi);
}

// ---------------- main: batched vector chain, B fragments via LDG.128 ----------
__global__ void __launch_bounds__(256) mps_chain(
    const float* __restrict__ x, const float* __restrict__ core0,
    const float* __restrict__ classifier, float* __restrict__ out)
{
    __shared__ char sm[SMEM_MAIN];
    uint32_t smb = smem_u32(sm);
    const int tid = threadIdx.x, lane = tid & 31, wc = tid >> 5;  // warp = 32-col slice
    const int b0 = blockIdx.x * 16;

    float* XS   = (float*)(sm + XS_OFF);    // [16][256]
    float* LOGS = (float*)(sm + LG_OFF);
    float* RINV = (float*)(sm + RI_OFF);
    float* LTOT = (float*)(sm + LT_OFF);

    #pragma unroll
    for (int it = 0; it < 16; ++it) {
        int idx = it * 256 + tid;
        XS[idx] = x[(size_t)(b0 + (idx >> 8)) * 256 + (idx & 255)];
    }
    if (tid < 16) LOGS[tid] = 0.f;
    __syncthreads();

    // init V[bb][h]
    #pragma unroll
    for (int it = 0; it < 8; ++it) {
        int idx = it * 256 + tid;
        int bb = idx >> 7, h = idx & 127;
        float xv = XS[bb * 256];
        float v = (1.f - xv) * core0[h] + xv * core0[HD + h];
        *(__nv_bfloat16*)(sm + V_OFF + bb * (PITCHV * 2) + h * 2) = __float2bfloat16(v);
    }
    // first barrier in the loop makes these visible

    const int l15 = lane & 15, lhi = (lane >> 4) << 3;
    const int r = lane >> 2, q = lane & 3;
    // per-thread base into the permuted fragment buffer (uint4 units):
    // ((wc*4 + nt)*4 + kp)*32 + lane, nt=kp=0 here
    const uint32_t fragbase = (uint32_t)(wc * 16) * 32 + lane;

    for (int m = 0; m < 255; ++m) {
        // ---- B fragments: 16 coalesced LDG.128 from L2, no V dependency ----
        const uint4* bp = (const uint4*)g_perm + ((size_t)m << 12) + fragbase;
        uint4 Bv[4][4];
        #pragma unroll
        for (int nt = 0; nt < 4; ++nt)
            #pragma unroll
            for (int kp = 0; kp < 4; ++kp)
                Bv[nt][kp] = bp[(nt * 4 + kp) * 32];

        __syncthreads();   // V(m) writes visible

        uint32_t A[8][4];
        #pragma unroll
        for (int kc = 0; kc < 8; ++kc)
            ldm_x4(A[kc], smb + V_OFF + (uint32_t)(l15 * PITCHV + kc * 16 + lhi) * 2);

        float acc[4][4];
        #pragma unroll
        for (int i = 0; i < 4; ++i)
            #pragma unroll
            for (int j = 0; j < 4; ++j) acc[i][j] = 0.f;

        #pragma unroll
        for (int kc = 0; kc < 8; ++kc)
            #pragma unroll
            for (int nt = 0; nt < 4; ++nt) {
                const uint4& v = Bv[nt][kc >> 1];
                uint32_t bb0 = (kc & 1) ? v.z : v.x;
                uint32_t bb1 = (kc & 1) ? v.w : v.y;
                mma16816(acc[nt], A[kc], bb0, bb1);
            }

        __syncthreads();   // all V reads done -> safe to overwrite

        const float xa = XS[r * 256 + m + 1];
        const float xb = XS[(r + 8) * 256 + m + 1];
        #pragma unroll
        for (int nt = 0; nt < 4; ++nt) {
            int h = wc * 16 + nt * 4 + q;
            float v0 = fmaf(xa, acc[nt][1], (1.f - xa) * acc[nt][0]);
            float v1 = fmaf(xb, acc[nt][3], (1.f - xb) * acc[nt][2]);
            *(__nv_bfloat16*)(sm + V_OFF + r * (PITCHV * 2) + h * 2) = __float2bfloat16(v0);
            *(__nv_bfloat16*)(sm + V_OFF + (r + 8) * (PITCHV * 2) + h * 2) = __float2bfloat16(v1);
        }

        if (((m + 1) & 15) == 0 && m < 254) {
            __syncthreads();
            int bb = tid >> 4, seg = tid & 15;
            __nv_bfloat16* vr = (__nv_bfloat16*)(sm + V_OFF + bb * (PITCHV * 2));
            float s = 0.f;
            #pragma unroll
            for (int j = 0; j < 8; ++j) {
                float f = __bfloat162float(vr[seg * 8 + j]);
                s = fmaf(f, f, s);
            }
            #pragma unroll
            for (int o = 8; o > 0; o >>= 1) s += __shfl_xor_sync(0xffffffffu, s, o);
            if (seg == 0) {
                float nrm = fmaxf(sqrtf(s), 1e-30f);
                LOGS[bb] += logf(nrm);
                RINV[bb] = 1.f / nrm;
            }
            __syncthreads();
            float ri = RINV[bb];
            #pragma unroll
            for (int j = 0; j < 8; ++j)
                vr[seg * 8 + j] = __float2bfloat16(__bfloat162float(vr[seg * 8 + j]) * ri);
        }
    }
    __syncthreads();

    // final norm + total log
    {
        int bb = tid >> 4, seg = tid & 15;
        const __nv_bfloat16* vr = (const __nv_bfloat16*)(sm + V_OFF + bb * (PITCHV * 2));
        float s = 0.f;
        #pragma unroll
        for (int j = 0; j < 8; ++j) {
            float f = __bfloat162float(vr[seg * 8 + j]);
            s = fmaf(f, f, s);
        }
        #pragma unroll
        for (int o = 8; o > 0; o >>= 1) s += __shfl_xor_sync(0xffffffffu, s, o);
        if (seg == 0) {
            float nrm = fmaxf(sqrtf(s), 1e-30f);
            RINV[bb] = 1.f / nrm;
            LTOT[bb] = LOGS[bb] + logf(nrm);
        }
    }
    __syncthreads();

    if (tid < 16 * OUTC) {
        int bb = tid / OUTC, o = tid % OUTC;
        const __nv_bfloat16* vr = (const __nv_bfloat16*)(sm + V_OFF + bb * (PITCHV * 2));
        float s = 0.f;
        #pragma unroll
        for (int h = 0; h < HD; ++h)
            s = fmaf(__bfloat162float(vr[h]), classifier[o * HD + h], s);
        out[(size_t)(b0 + bb) * OUTC + o] = s * RINV[bb] + LTOT[bb];
    }
}

extern "C" void kernel_launch(void* const* d_in, const int* in_sizes, int n_in,
                              void* d_out, int out_size)
{
    (void)in_sizes; (void)n_in; (void)out_size;
    const float* x          = (const float*)d_in[0];
    const float* core0      = (const float*)d_in[1];
    const float* cores      = (const float*)d_in[2];
    const float* classifier = (const float*)d_in[3];
    float*       out        = (float*)d_out;

    conv_perm<<<16320, 256>>>(cores);      // 255*16384 threads
    mps_chain<<<4, 256>>>(x, core0, classifier, out);
}

// round 9
// speedup vs baseline: 3.3680x; 1.3429x over previous
#include <cuda_runtime.h>
#include <cuda_bf16.h>
#include <math.h>
#include <stdint.h>

#define BATCH  64
#define HD     128
#define OUTC   10

#define PITCHV 136      // V row pitch, bf16 elems
#define V0_OFF 0
#define V1_OFF (16 * PITCHV * 2)            // 4352
#define XS_OFF (2 * 16 * PITCHV * 2)        // 8704
#define LG_OFF (XS_OFF + 16 * 256 * 4)      // 25088
#define RI_OFF (LG_OFF + 64)
#define LT_OFF (RI_OFF + 64)
#define SMEM_MAIN (LT_OFF + 64)             // ~25.3 KB (static)

// Chain matrices permuted into mma.m16n8k16 B-fragment order (bf16, 16.7 MB):
// uint32 index: (((m*8 + wc)*4 + nt)*4 + kp)*128 + lane*4 + j      [16384 u32 per m]
//   kc = 2*kp + (j>>1); reg = j&1
//   packed pair = M[k0][n], M[k0+1][n]; k0 = kc*16 + 2*(lane&3) + reg*8
//   n = wc*32 + nt*8 + (lane>>2);  M[k][2h+d] = cores[m][k][d][h]
__device__ uint32_t g_perm[(size_t)255 * 16384];

// ---------------- helpers ----------------
__device__ __forceinline__ uint32_t smem_u32(const void* p) {
    uint32_t a;
    asm("{ .reg .u64 t; cvta.to.shared.u64 t, %1; cvt.u32.u64 %0, t; }" : "=r"(a) : "l"(p));
    return a;
}
__device__ __forceinline__ void ldm_x4(uint32_t* r, uint32_t addr) {
    asm volatile("ldmatrix.sync.aligned.m8n8.x4.shared.b16 {%0,%1,%2,%3}, [%4];"
                 : "=r"(r[0]), "=r"(r[1]), "=r"(r[2]), "=r"(r[3]) : "r"(addr));
}
__device__ __forceinline__ void mma16816(float* c, const uint32_t* a,
                                         uint32_t b0, uint32_t b1) {
    asm volatile(
        "mma.sync.aligned.m16n8k16.row.col.f32.bf16.bf16.f32 "
        "{%0,%1,%2,%3}, {%4,%5,%6,%7}, {%8,%9}, {%0,%1,%2,%3};"
        : "+f"(c[0]), "+f"(c[1]), "+f"(c[2]), "+f"(c[3])
        : "r"(a[0]), "r"(a[1]), "r"(a[2]), "r"(a[3]), "r"(b0), "r"(b1));
}
__device__ __forceinline__ uint32_t packbf2(float a, float b) {
    __nv_bfloat162 t = __floats2bfloat162_rn(a, b);
    return *reinterpret_cast<uint32_t*>(&t);
}

// ---------------- pre-pass: cores fp32 -> fragment-permuted bf16 ----------------
__global__ void __launch_bounds__(256) conv_perm(const float* __restrict__ cores)
{
    size_t gid = (size_t)blockIdx.x * 256 + threadIdx.x;   // 255*16384 total
    int u = (int)(gid & 16383);
    int m = (int)(gid >> 14);
    int j    = u & 3;
    int lane = (u >> 2) & 31;
    int kp   = (u >> 7) & 3;
    int nt   = (u >> 9) & 3;
    int wc   = (u >> 11) & 7;
    int kc = 2 * kp + (j >> 1);
    int k0 = kc * 16 + 2 * (lane & 3) + ((j & 1) << 3);
    int n  = wc * 32 + nt * 8 + (lane >> 2);
    int h = n >> 1, d = n & 1;
    const float* base = cores + (size_t)m * 32768;
    float lo = base[((size_t)k0 * 2 + d) * 128 + h];
    float hi = base[((size_t)(k0 + 1) * 2 + d) * 128 + h];
    g_perm[gid] = packbf2(lo, hi);
}

// ---------------- one chain step (inlined; B double-buffered in regs) --------
__device__ __forceinline__ void chain_step(
    int m, bool prefetch, uint4* __restrict__ Bcur, uint4* __restrict__ Bnext,
    char* sm, uint32_t smb, uint32_t fragbase,
    int lane, int wc, int l15, int lhi, int r, int q)
{
    float* XS   = (float*)(sm + XS_OFF);
    float* LOGS = (float*)(sm + LG_OFF);
    float* RINV = (float*)(sm + RI_OFF);

    // ---- prefetch B(m+1) into Bnext: 16 coalesced LDG.128 (consumed next step)
    if (prefetch) {
        const uint4* bp = (const uint4*)g_perm + ((size_t)(m + 1) << 12) + fragbase;
        #pragma unroll
        for (int i = 0; i < 16; ++i)
            Bnext[i] = bp[i * 32];
    }

    const uint32_t vr = smb + ((m & 1) ? V1_OFF : V0_OFF);   // read buffer
    char* vw = sm + ((m & 1) ? V0_OFF : V1_OFF);             // write buffer

    __syncthreads();   // V(m) writes (prev step / init) visible

    uint32_t A[8][4];
    #pragma unroll
    for (int kc = 0; kc < 8; ++kc)
        ldm_x4(A[kc], vr + (uint32_t)(l15 * PITCHV + kc * 16 + lhi) * 2);

    float acc[4][4];
    #pragma unroll
    for (int i = 0; i < 4; ++i)
        #pragma unroll
        for (int j = 0; j < 4; ++j) acc[i][j] = 0.f;

    #pragma unroll
    for (int kc = 0; kc < 8; ++kc)
        #pragma unroll
        for (int nt = 0; nt < 4; ++nt) {
            const uint4& v = Bcur[nt * 4 + (kc >> 1)];
            uint32_t b0 = (kc & 1) ? v.z : v.x;
            uint32_t b1 = (kc & 1) ? v.w : v.y;
            mma16816(acc[nt], A[kc], b0, b1);
        }

    // epilogue -> write buffer (no barrier: ping-pong)
    const float xa = XS[r * 256 + m + 1];
    const float xb = XS[(r + 8) * 256 + m + 1];
    #pragma unroll
    for (int nt = 0; nt < 4; ++nt) {
        int h = wc * 16 + nt * 4 + q;
        float v0 = fmaf(xa, acc[nt][1], (1.f - xa) * acc[nt][0]);
        float v1 = fmaf(xb, acc[nt][3], (1.f - xb) * acc[nt][2]);
        *(__nv_bfloat16*)(vw + r * (PITCHV * 2) + h * 2) = __float2bfloat16(v0);
        *(__nv_bfloat16*)(vw + (r + 8) * (PITCHV * 2) + h * 2) = __float2bfloat16(v1);
    }

    // periodic renormalization on the write buffer
    if (((m + 1) & 15) == 0 && m < 254) {
        const int tid = threadIdx.x;
        __syncthreads();
        int bb = tid >> 4, seg = tid & 15;
        __nv_bfloat16* vrow = (__nv_bfloat16*)(vw + bb * (PITCHV * 2));
        float s = 0.f;
        #pragma unroll
        for (int j = 0; j < 8; ++j) {
            float f = __bfloat162float(vrow[seg * 8 + j]);
            s = fmaf(f, f, s);
        }
        #pragma unroll
        for (int o = 8; o > 0; o >>= 1) s += __shfl_xor_sync(0xffffffffu, s, o);
        if (seg == 0) {
            float nrm = fmaxf(sqrtf(s), 1e-30f);
            LOGS[bb] += logf(nrm);
            RINV[bb] = 1.f / nrm;
        }
        __syncthreads();
        float ri = RINV[bb];
        #pragma unroll
        for (int j = 0; j < 8; ++j)
            vrow[seg * 8 + j] = __float2bfloat16(__bfloat162float(vrow[seg * 8 + j]) * ri);
        // visibility of rescaled V covered by next step's leading barrier
    }
}

// ---------------- main: batched vector chain ----------------
__global__ void __launch_bounds__(256, 1) mps_chain(
    const float* __restrict__ x, const float* __restrict__ core0,
    const float* __restrict__ classifier, float* __restrict__ out)
{
    __shared__ char sm[SMEM_MAIN];
    uint32_t smb = smem_u32(sm);
    const int tid = threadIdx.x, lane = tid & 31, wc = tid >> 5;
    const int b0 = blockIdx.x * 16;

    float* XS   = (float*)(sm + XS_OFF);
    float* LOGS = (float*)(sm + LG_OFF);
    float* RINV = (float*)(sm + RI_OFF);
    float* LTOT = (float*)(sm + LT_OFF);

    #pragma unroll
    for (int it = 0; it < 16; ++it) {
        int idx = it * 256 + tid;
        XS[idx] = x[(size_t)(b0 + (idx >> 8)) * 256 + (idx & 255)];
    }
    if (tid < 16) LOGS[tid] = 0.f;
    __syncthreads();

    // init V0[bb][h]
    #pragma unroll
    for (int it = 0; it < 8; ++it) {
        int idx = it * 256 + tid;
        int bb = idx >> 7, h = idx & 127;
        float xv = XS[bb * 256];
        float v = (1.f - xv) * core0[h] + xv * core0[HD + h];
        *(__nv_bfloat16*)(sm + V0_OFF + bb * (PITCHV * 2) + h * 2) = __float2bfloat16(v);
    }
    // step 0's leading barrier covers visibility

    const int l15 = lane & 15, lhi = (lane >> 4) << 3;
    const int r = lane >> 2, q = lane & 3;
    const uint32_t fragbase = (uint32_t)(wc * 16) * 32 + lane;

    // preload B(0)
    uint4 B0[16], B1[16];
    {
        const uint4* bp = (const uint4*)g_perm + fragbase;
        #pragma unroll
        for (int i = 0; i < 16; ++i) B0[i] = bp[i * 32];
    }

    // 127 unrolled pairs + final step (m=254 uses B0, loaded during m=253)
    for (int mm = 0; mm < 127; ++mm) {
        chain_step(2 * mm,     true, B0, B1, sm, smb, fragbase, lane, wc, l15, lhi, r, q);
        chain_step(2 * mm + 1, true, B1, B0, sm, smb, fragbase, lane, wc, l15, lhi, r, q);
    }
    chain_step(254, false, B0, B1, sm, smb, fragbase, lane, wc, l15, lhi, r, q);
    __syncthreads();

    // final V lives in buffer (255 & 1) = V1
    {
        int bb = tid >> 4, seg = tid & 15;
        const __nv_bfloat16* vrow = (const __nv_bfloat16*)(sm + V1_OFF + bb * (PITCHV * 2));
        float s = 0.f;
        #pragma unroll
        for (int j = 0; j < 8; ++j) {
            float f = __bfloat162float(vrow[seg * 8 + j]);
            s = fmaf(f, f, s);
        }
        #pragma unroll
        for (int o = 8; o > 0; o >>= 1) s += __shfl_xor_sync(0xffffffffu, s, o);
        if (seg == 0) {
            float nrm = fmaxf(sqrtf(s), 1e-30f);
            RINV[bb] = 1.f / nrm;
            LTOT[bb] = LOGS[bb] + logf(nrm);
        }
    }
    __syncthreads();

    if (tid < 16 * OUTC) {
        int bb = tid / OUTC, o = tid % OUTC;
        const __nv_bfloat16* vrow = (const __nv_bfloat16*)(sm + V1_OFF + bb * (PITCHV * 2));
        float s = 0.f;
        #pragma unroll
        for (int h = 0; h < HD; ++h)
            s = fmaf(__bfloat162float(vrow[h]), classifier[o * HD + h], s);
        out[(size_t)(b0 + bb) * OUTC + o] = s * RINV[bb] + LTOT[bb];
    }
}

extern "C" void kernel_launch(void* const* d_in, const int* in_sizes, int n_in,
                              void* d_out, int out_size)
{
    (void)in_sizes; (void)n_in; (void)out_size;
    const float* x          = (const float*)d_in[0];
    const float* core0      = (const float*)d_in[1];
    const float* cores      = (const float*)d_in[2];
    const float* classifier = (const float*)d_in[3];
    float*       out        = (float*)d_out;

    conv_perm<<<16320, 256>>>(cores);      // 255*16384 threads
    mps_chain<<<4, 256>>>(x, core0, classifier, out);
}